// round 16
// baseline (speedup 1.0000x reference)
#include <cuda_runtime.h>
#include <cstdint>

#define BATCH   32
#define NPRED   22743
#define NCLS    80
#define KTOP    300
#define STRIDE  85
#define CAP     512
#define NBUCK   4096
#define RPC     2048    // rows per CTA in k1 (512 threads x 4)
#define NCTA1   12      // ceil(NPRED / RPC)

// global scratch — zero at module load; every pass restores its own zeros
__device__ unsigned int       g_keys[BATCH * NPRED];
__device__ unsigned int       g_hist[BATCH * NBUCK];
__device__ unsigned int       g_cnt[BATCH];
__device__ unsigned long long g_cand[BATCH * CAP];
__device__ float2             g_ls[BATCH * KTOP];        // (label, score) per rank
__device__ unsigned int       g_done1[BATCH];            // last-block counters
__device__ unsigned int       g_done2[BATCH];

__device__ __forceinline__ unsigned int bucket_of(unsigned int key) {
    // key in (0x3F000000, 0x3F800000]  (conf in (0.5, 1.0])
    return min((key - 0x3F000000u) >> 11, (unsigned)(NBUCK - 1));
}

// ---------------------------------------------------------------------------
// k1: conf scan via cp.async (deep MLP), then the last CTA per batch computes
// threshold + compaction + scratch re-zero. (Byte-identical to passing R12 k1.)
// ---------------------------------------------------------------------------
__global__ __launch_bounds__(512) void k1(const float* __restrict__ p) {
    const int b    = blockIdx.y;
    const int tid  = threadIdx.x;
    const int lane = tid & 31;
    const int wrp  = tid >> 5;

    __shared__ float sbuf[RPC];   // 8 KB staging for cp.async

    // ---- phase 1: 4 cp.async per thread, all in flight simultaneously ----
    {
        const int n0 = blockIdx.x * RPC + tid;
        const float* base = p + (size_t)b * NPRED * STRIDE + 4;
#pragma unroll
        for (int k = 0; k < 4; k++) {
            int n = n0 + k * 512;
            if (n < NPRED) {
                unsigned int dst =
                    (unsigned int)__cvta_generic_to_shared(&sbuf[tid + k * 512]);
                const float* src = base + (size_t)n * STRIDE;
                asm volatile("cp.async.ca.shared.global [%0], [%1], 4;"
                             :: "r"(dst), "l"(src));
            }
        }
        asm volatile("cp.async.commit_group;");
        asm volatile("cp.async.wait_group 0;");
        // each thread consumes only its own slots — no __syncthreads needed
#pragma unroll
        for (int k = 0; k < 4; k++) {
            int n = n0 + k * 512;
            if (n < NPRED) {
                float x = sbuf[tid + k * 512];
                unsigned int key = 0;
                if (x > 0.0f) {
                    float c = 1.0f / (1.0f + expf(-x));
                    if (c > 0.5f) key = __float_as_uint(c);   // conf > THR_CONF
                }
                g_keys[b * NPRED + n] = key;
                if (key) atomicAdd(&g_hist[b * NBUCK + bucket_of(key)], 1u);
            }
        }
    }

    // ---- last-block election (deadlock-free: sole winner continues) ----
    __shared__ int isLast;
    __threadfence();
    __syncthreads();
    if (tid == 0) isLast = (atomicAdd(&g_done1[b], 1u) == NCTA1 - 1);
    __syncthreads();
    if (!isLast) return;
    __threadfence();   // acquire: all batch-b writes visible

    // ---- threshold: suffix scan over 4096 buckets ----
    __shared__ unsigned int wsum[16], wsuf[17];
    __shared__ unsigned int sTotal;
    __shared__ int sT, scnt;
    if (tid == 0) { scnt = 0; sTotal = 0; }

    const unsigned int* h = g_hist + b * NBUCK;
    unsigned int v[8], s8 = 0;
#pragma unroll
    for (int i = 0; i < 8; i++) { v[i] = __ldg(h + tid * 8 + i); s8 += v[i]; }

    unsigned int suf = s8;
#pragma unroll
    for (int o = 1; o < 32; o <<= 1) {
        unsigned int t = __shfl_down_sync(0xffffffffu, suf, o);
        if (lane + o < 32) suf += t;
    }
    if (lane == 0) wsum[wrp] = suf;
    __syncthreads();
    if (wrp == 0) {   // whole warp participates — shfl legal
        unsigned int ws = (lane < 16) ? wsum[lane] : 0u;
#pragma unroll
        for (int o = 1; o < 32; o <<= 1) {
            unsigned int t = __shfl_down_sync(0xffffffffu, ws, o);
            if (lane + o < 32) ws += t;
        }
        if (lane < 16) wsuf[lane] = ws;
        if (lane == 0) { wsuf[16] = 0; sTotal = ws; }
    }
    __syncthreads();
    {
        unsigned int total = sTotal;
        unsigned int Kcap  = min((unsigned)KTOP, total);
        unsigned int inc   = suf + wsuf[wrp + 1];
        unsigned int above = inc - s8;
        if (Kcap > 0 && inc >= Kcap && above < Kcap) {
            unsigned int run = above;
            int T = tid * 8;
#pragma unroll
            for (int i = 7; i >= 0; i--) {
                run += v[i];
                if (run >= Kcap) { T = tid * 8 + i; break; }
            }
            sT = T;
        }
        if (Kcap == 0 && tid == 0) sT = NBUCK;
    }
    __syncthreads();
    const int T = sT;

    // ---- compaction (~303 survivors), L2-hot keys, 4-way MLP ----
    const unsigned int* kb = g_keys + (size_t)b * NPRED;
    for (int k0 = 0; k0 < 48; k0 += 4) {           // 48*512 = 24576 >= NPRED
        unsigned int kv[4] = {0u, 0u, 0u, 0u};
#pragma unroll
        for (int j = 0; j < 4; j++) {
            int n = tid + (k0 + j) * 512;
            if (n < NPRED) kv[j] = __ldg(kb + n);
        }
#pragma unroll
        for (int j = 0; j < 4; j++) {
            unsigned int key = kv[j];
            if (key && (int)bucket_of(key) >= T) {
                int n = tid + (k0 + j) * 512;
                int pos = atomicAdd(&scnt, 1);
                if (pos < CAP)
                    g_cand[b * CAP + pos] = ((unsigned long long)key << 32) |
                                            (0xFFFFFFFFu - (unsigned)n);
            }
        }
    }
    __syncthreads();
    int cc = min(scnt, CAP);
    if (tid < CAP && tid >= cc) g_cand[b * CAP + tid] = 0ull;   // zero-fill tail
    if (tid == 0) g_cnt[b] = (unsigned)cc;

    // ---- restore zeros for next pass ----
    for (int i = tid; i < NBUCK; i += 512) g_hist[b * NBUCK + i] = 0u;
    if (tid == 0) g_done1[b] = 0u;
}

// ---------------------------------------------------------------------------
// k2: rank + decode + argmax (grid (8,32)); ALL shuffles are executed
// unconditionally (inactive lanes contribute neutral values) so warp
// convergence stays fully defined across the later barriers. The LAST CTA
// per batch then runs the IoU mask + greedy NMS + outputs in SMEM.
// ---------------------------------------------------------------------------
__global__ __launch_bounds__(512) void k2(const float* __restrict__ p,
                                          const float* __restrict__ ancs,
                                          const float* __restrict__ fsz,
                                          float* __restrict__ outIds,
                                          float* __restrict__ outBoxes,
                                          float* __restrict__ outLabels,
                                          float* __restrict__ outScores) {
    const int chunk = blockIdx.x;       // 0..7
    const int b     = blockIdx.y;
    const int tid   = threadIdx.x;

    // ===== phase A: rank + decode for this CTA's 64 slots =====
    {
        const int sub  = tid & 7;
        const int grp  = tid >> 3;          // 0..63
        const int slot = chunk * 64 + grp;  // 0..511

        __shared__ unsigned long long sc[CAP];
        sc[tid] = g_cand[b * CAP + tid];
        __syncthreads();

        unsigned long long my = sc[slot];

        int r = 0;
#pragma unroll 8
        for (int j = sub; j < CAP; j += 8) r += (sc[j] > my);
        r += __shfl_down_sync(0xffffffffu, r, 4, 8);
        r += __shfl_down_sync(0xffffffffu, r, 2, 8);
        r += __shfl_down_sync(0xffffffffu, r, 1, 8);
        r  = __shfl_sync(0xffffffffu, r, 0, 8);

        const bool act = (my != 0ull) && (r < KTOP);
        const int  n   = act ? (int)(0xFFFFFFFFu - (unsigned int)(my & 0xFFFFFFFFull)) : 0;
        const float* pr = p + ((size_t)b * NPRED + n) * STRIDE;

        unsigned long long best = 0ull;
        if (act) {
#pragma unroll
            for (int k = 0; k < 10; k++) {
                int c = sub + k * 8;
                unsigned int ub = __float_as_uint(__ldg(pr + 5 + c));
                ub = (ub & 0x80000000u) ? ~ub : (ub | 0x80000000u);   // order-preserving
                unsigned long long key = ((unsigned long long)ub << 8) |
                                         (unsigned)(255 - c);
                if (key > best) best = key;
            }
        }
        // UNCONDITIONAL reduction — every lane executes every shfl
        {
            unsigned long long t;
            t = __shfl_down_sync(0xffffffffu, best, 4, 8); if (t > best) best = t;
            t = __shfl_down_sync(0xffffffffu, best, 2, 8); if (t > best) best = t;
            t = __shfl_down_sync(0xffffffffu, best, 1, 8); if (t > best) best = t;
        }
        if (act && sub == 0) {
            int label = 256 - (int)(best & 0xFFull);   // argmax + 1, tie -> lowest
            float tx = __ldg(pr + 0), ty = __ldg(pr + 1);
            float tw = __ldg(pr + 2), th = __ldg(pr + 3);
            float fs = __ldg(fsz + (size_t)n * 2);
            float4 an = *reinterpret_cast<const float4*>(ancs + (size_t)n * 4);
            float cx = 1.0f / (1.0f + expf(-tx)) / fs + an.x;
            float cy = 1.0f / (1.0f + expf(-ty)) / fs + an.y;
            float w  = expf(tw) * an.z;
            float hh = expf(th) * an.w;
            *reinterpret_cast<float4*>(outBoxes + (size_t)(b * KTOP + r) * 4) =
                make_float4(cx - 0.5f * w, cy - 0.5f * hh,
                            cx + 0.5f * w, cy + 0.5f * hh);
            g_ls[b * KTOP + r] =
                make_float2((float)label, __uint_as_float((unsigned int)(my >> 32)));
        }
    }

    // ===== last-block election =====
    __shared__ int isLast;
    __threadfence();
    __syncthreads();
    if (tid == 0) isLast = (atomicAdd(&g_done2[b], 1u) == 7);
    __syncthreads();
    if (!isLast) return;
    __threadfence();   // acquire: all batch-b boxes/ls visible

    // ===== tail: NMS for batch b, entirely in SMEM =====
    __shared__ float sl[KTOP], st[KTOP], sr[KTOP], sb[KTOP], sa[KTOP], ssc[KTOP];
    __shared__ int   slab[KTOP];
    __shared__ unsigned long long supp[KTOP][5];   // 12 KB
    __shared__ unsigned long long anyLow[5], keepw[5];

    if (tid < 5) anyLow[tid] = 0ull;
    const int cc = min((int)g_cnt[b], KTOP);

    if (tid < KTOP) {
        if (tid < cc) {
            float4 bx = *reinterpret_cast<const float4*>(
                outBoxes + (size_t)(b * KTOP + tid) * 4);
            float2 ls = g_ls[b * KTOP + tid];
            float off = 4.0f * ls.x;
            float l = bx.x + off, t0 = bx.y + off, r = bx.z + off, bt = bx.w + off;
            sl[tid] = l; st[tid] = t0; sr[tid] = r; sb[tid] = bt;
            sa[tid] = fmaxf(r - l, 0.0f) * fmaxf(bt - t0, 0.0f);
            ssc[tid]  = ls.y;
            slab[tid] = (int)ls.x;
        } else {   // pathological pad (never with this data)
            sl[tid] = st[tid] = sr[tid] = sb[tid] = sa[tid] = 0.f;
            ssc[tid] = 0.f; slab[tid] = 0;
            *reinterpret_cast<float4*>(outBoxes + (size_t)(b * KTOP + tid) * 4) =
                make_float4(0.f, 0.f, 0.f, 0.f);
        }
    }
    __syncthreads();

    // ---- suppression bitmask: 1500 tasks over 512 threads ----
    for (int task = tid; task < KTOP * 5; task += 512) {
        int i = task % KTOP, w = task / KTOP;
        float li = sl[i], ti = st[i], ri = sr[i], bi = sb[i], ai = sa[i];
        unsigned long long bits = 0ull;
        int j0 = w * 64;
        int jend = min(j0 + 64, KTOP);
        for (int j = j0; j < jend; j++) {
            float ltx = fmaxf(li, sl[j]);
            float lty = fmaxf(ti, st[j]);
            float rbx = fminf(ri, sr[j]);
            float rby = fminf(bi, sb[j]);
            float iw = fmaxf(rbx - ltx, 0.0f);
            float ih = fmaxf(rby - lty, 0.0f);
            float inter = iw * ih;
            float iou = inter / (ai + sa[j] - inter + 1e-7f);
            if (iou > 0.3f) bits |= 1ull << (j - j0);
        }
        supp[i][w] = bits;
        unsigned long long low = 0ull;      // suppressors with j < i
        int iw6 = i >> 6;
        if (w < iw6)       low = bits;
        else if (w == iw6) low = bits & ((1ull << (i & 63)) - 1ull);
        if (low) atomicOr(&anyLow[iw6], 1ull << (i & 63));
    }
    __syncthreads();

    // ---- greedy scan (valid = rank < cc) ----
    if (tid == 0) {
        unsigned long long kw[5] = {0ull, 0ull, 0ull, 0ull, 0ull};
#pragma unroll
        for (int w = 0; w < 5; w++) {
            unsigned long long cur = 0ull;
            unsigned long long alw = anyLow[w];
            int lo = w * 64;
            int hi = min(cc, lo + 64);
            unsigned long long vmw = 0ull;
            if (hi > lo) {
                int nb = hi - lo;
                vmw = (nb >= 64) ? ~0ull : ((1ull << nb) - 1ull);
            }
            int jend = (w < 4) ? 64 : (KTOP - 256);
            for (int jj = 0; jj < jend; jj++) {
                unsigned long long bit = 1ull << jj;
                if (vmw & bit) {
                    if (!(alw & bit)) {
                        cur |= bit;        // no lower-ranked overlap at all
                    } else {
                        int i = w * 64 + jj;
                        unsigned long long s = (supp[i][0] & kw[0]) |
                                               (supp[i][1] & kw[1]) |
                                               (supp[i][2] & kw[2]) |
                                               (supp[i][3] & kw[3]) |
                                               (supp[i][4] & kw[4]) |
                                               (supp[i][w] & cur);
                        if (s == 0ull) cur |= bit;
                    }
                }
            }
            kw[w] = cur;
        }
#pragma unroll
        for (int w = 0; w < 5; w++) keepw[w] = kw[w];
    }
    __syncthreads();

    // ---- final writes + scratch reset ----
    if (tid < KTOP) {
        bool kp = (keepw[tid >> 6] >> (tid & 63)) & 1ull;
        outIds[b * KTOP + tid]    = (float)b;
        outScores[b * KTOP + tid] = kp ? ssc[tid] : 0.0f;
        outLabels[b * KTOP + tid] = kp ? (float)slab[tid] : 0.0f;
    }
    if (tid == 0) g_done2[b] = 0u;
}

// ---------------------------------------------------------------------------
extern "C" void kernel_launch(void* const* d_in, const int* in_sizes, int n_in,
                              void* d_out, int out_size) {
    const float* p    = (const float*)d_in[0];
    const float* ancs = (const float*)d_in[1];
    const float* fsz  = (const float*)d_in[2];
    float* out = (float*)d_out;

    float* outIds    = out;
    float* outBoxes  = out + BATCH * KTOP;
    float* outLabels = out + BATCH * KTOP * 5;
    float* outScores = out + BATCH * KTOP * 6;

    dim3 grid1(NCTA1, BATCH);      // 12 x 32
    k1<<<grid1, 512>>>(p);
    dim3 grid2(CAP / 64, BATCH);   // 8 x 32
    k2<<<grid2, 512>>>(p, ancs, fsz, outIds, outBoxes, outLabels, outScores);
}

// round 17
// speedup vs baseline: 1.7996x; 1.7996x over previous
#include <cuda_runtime.h>
#include <cstdint>

#define BATCH   32
#define NPRED   22743
#define NCLS    80
#define KTOP    300
#define STRIDE  85
#define CAP     512
#define NBUCK   4096
#define RPC     2048    // rows per CTA in k1 (512 threads x 4)
#define NCTA1   12      // ceil(NPRED / RPC)

// global scratch — zero at module load; every pass restores its own zeros
__device__ unsigned int       g_keys[BATCH * NPRED];
__device__ unsigned int       g_hist[BATCH * NBUCK];
__device__ unsigned int       g_cnt[BATCH];
__device__ unsigned long long g_cand[BATCH * CAP];
__device__ float2             g_ls[BATCH * KTOP];        // (label, score) per rank
__device__ unsigned long long g_supp[BATCH * KTOP * 5];
__device__ unsigned long long g_anyLow[BATCH * 5];
__device__ unsigned int       g_done1[BATCH];            // last-block counters
__device__ unsigned int       g_done3[BATCH];

__device__ __forceinline__ unsigned int bucket_of(unsigned int key) {
    // key in (0x3F000000, 0x3F800000]  (conf in (0.5, 1.0])
    return min((key - 0x3F000000u) >> 11, (unsigned)(NBUCK - 1));
}

// ---------------------------------------------------------------------------
// k1: conf scan via cp.async, then the last CTA per batch computes threshold +
// compaction + scratch re-zero. (Byte-identical to the R12-passing k1.)
// ---------------------------------------------------------------------------
__global__ __launch_bounds__(512) void k1(const float* __restrict__ p) {
    const int b    = blockIdx.y;
    const int tid  = threadIdx.x;
    const int lane = tid & 31;
    const int wrp  = tid >> 5;

    __shared__ float sbuf[RPC];   // 8 KB staging for cp.async

    {
        const int n0 = blockIdx.x * RPC + tid;
        const float* base = p + (size_t)b * NPRED * STRIDE + 4;
#pragma unroll
        for (int k = 0; k < 4; k++) {
            int n = n0 + k * 512;
            if (n < NPRED) {
                unsigned int dst =
                    (unsigned int)__cvta_generic_to_shared(&sbuf[tid + k * 512]);
                const float* src = base + (size_t)n * STRIDE;
                asm volatile("cp.async.ca.shared.global [%0], [%1], 4;"
                             :: "r"(dst), "l"(src));
            }
        }
        asm volatile("cp.async.commit_group;");
        asm volatile("cp.async.wait_group 0;");
#pragma unroll
        for (int k = 0; k < 4; k++) {
            int n = n0 + k * 512;
            if (n < NPRED) {
                float x = sbuf[tid + k * 512];
                unsigned int key = 0;
                if (x > 0.0f) {
                    float c = 1.0f / (1.0f + expf(-x));
                    if (c > 0.5f) key = __float_as_uint(c);   // conf > THR_CONF
                }
                g_keys[b * NPRED + n] = key;
                if (key) atomicAdd(&g_hist[b * NBUCK + bucket_of(key)], 1u);
            }
        }
    }

    // last-block election (deadlock-free: sole winner continues)
    __shared__ int isLast;
    __threadfence();
    __syncthreads();
    if (tid == 0) isLast = (atomicAdd(&g_done1[b], 1u) == NCTA1 - 1);
    __syncthreads();
    if (!isLast) return;
    __threadfence();

    // threshold: suffix scan over 4096 buckets
    __shared__ unsigned int wsum[16], wsuf[17];
    __shared__ unsigned int sTotal;
    __shared__ int sT, scnt;
    if (tid == 0) { scnt = 0; sTotal = 0; }

    const unsigned int* h = g_hist + b * NBUCK;
    unsigned int v[8], s8 = 0;
#pragma unroll
    for (int i = 0; i < 8; i++) { v[i] = __ldg(h + tid * 8 + i); s8 += v[i]; }

    unsigned int suf = s8;
#pragma unroll
    for (int o = 1; o < 32; o <<= 1) {
        unsigned int t = __shfl_down_sync(0xffffffffu, suf, o);
        if (lane + o < 32) suf += t;
    }
    if (lane == 0) wsum[wrp] = suf;
    __syncthreads();
    if (wrp == 0) {
        unsigned int ws = (lane < 16) ? wsum[lane] : 0u;
#pragma unroll
        for (int o = 1; o < 32; o <<= 1) {
            unsigned int t = __shfl_down_sync(0xffffffffu, ws, o);
            if (lane + o < 32) ws += t;
        }
        if (lane < 16) wsuf[lane] = ws;
        if (lane == 0) { wsuf[16] = 0; sTotal = ws; }
    }
    __syncthreads();
    {
        unsigned int total = sTotal;
        unsigned int Kcap  = min((unsigned)KTOP, total);
        unsigned int inc   = suf + wsuf[wrp + 1];
        unsigned int above = inc - s8;
        if (Kcap > 0 && inc >= Kcap && above < Kcap) {
            unsigned int run = above;
            int T = tid * 8;
#pragma unroll
            for (int i = 7; i >= 0; i--) {
                run += v[i];
                if (run >= Kcap) { T = tid * 8 + i; break; }
            }
            sT = T;
        }
        if (Kcap == 0 && tid == 0) sT = NBUCK;
    }
    __syncthreads();
    const int T = sT;

    // compaction (~303 survivors), L2-hot keys, 4-way MLP
    const unsigned int* kb = g_keys + (size_t)b * NPRED;
    for (int k0 = 0; k0 < 48; k0 += 4) {
        unsigned int kv[4] = {0u, 0u, 0u, 0u};
#pragma unroll
        for (int j = 0; j < 4; j++) {
            int n = tid + (k0 + j) * 512;
            if (n < NPRED) kv[j] = __ldg(kb + n);
        }
#pragma unroll
        for (int j = 0; j < 4; j++) {
            unsigned int key = kv[j];
            if (key && (int)bucket_of(key) >= T) {
                int n = tid + (k0 + j) * 512;
                int pos = atomicAdd(&scnt, 1);
                if (pos < CAP)
                    g_cand[b * CAP + pos] = ((unsigned long long)key << 32) |
                                            (0xFFFFFFFFu - (unsigned)n);
            }
        }
    }
    __syncthreads();
    int cc = min(scnt, CAP);
    if (tid < CAP && tid >= cc) g_cand[b * CAP + tid] = 0ull;
    if (tid == 0) g_cnt[b] = (unsigned)cc;

    for (int i = tid; i < NBUCK; i += 512) g_hist[b * NBUCK + i] = 0u;
    if (tid == 0) g_done1[b] = 0u;
}

// ---------------------------------------------------------------------------
// k2: full-chip rank + decode + argmax. grid (16,32), 256 thr, 32 slots/CTA.
// All shuffles unconditional (UB-free form proven in R16).
// ---------------------------------------------------------------------------
__global__ __launch_bounds__(256) void k2(const float* __restrict__ p,
                                          const float* __restrict__ ancs,
                                          const float* __restrict__ fsz,
                                          float* __restrict__ outBoxes) {
    const int chunk = blockIdx.x;       // 0..15
    const int b     = blockIdx.y;
    const int tid   = threadIdx.x;
    const int sub   = tid & 7;
    const int grp   = tid >> 3;         // 0..31
    const int slot  = chunk * 32 + grp; // 0..511

    __shared__ unsigned long long sc[CAP];
    sc[tid]       = g_cand[b * CAP + tid];
    sc[tid + 256] = g_cand[b * CAP + tid + 256];
    __syncthreads();

    unsigned long long my = sc[slot];

    int r = 0;
#pragma unroll 8
    for (int j = sub; j < CAP; j += 8) r += (sc[j] > my);
    r += __shfl_down_sync(0xffffffffu, r, 4, 8);
    r += __shfl_down_sync(0xffffffffu, r, 2, 8);
    r += __shfl_down_sync(0xffffffffu, r, 1, 8);
    r  = __shfl_sync(0xffffffffu, r, 0, 8);

    const bool act = (my != 0ull) && (r < KTOP);
    const int  n   = act ? (int)(0xFFFFFFFFu - (unsigned int)(my & 0xFFFFFFFFull)) : 0;
    const float* pr = p + ((size_t)b * NPRED + n) * STRIDE;

    unsigned long long best = 0ull;
    if (act) {
#pragma unroll
        for (int k = 0; k < 10; k++) {
            int c = sub + k * 8;
            unsigned int ub = __float_as_uint(__ldg(pr + 5 + c));
            ub = (ub & 0x80000000u) ? ~ub : (ub | 0x80000000u);   // order-preserving
            unsigned long long key = ((unsigned long long)ub << 8) | (unsigned)(255 - c);
            if (key > best) best = key;
        }
    }
    // UNCONDITIONAL reduction — every lane executes every shfl
    {
        unsigned long long t;
        t = __shfl_down_sync(0xffffffffu, best, 4, 8); if (t > best) best = t;
        t = __shfl_down_sync(0xffffffffu, best, 2, 8); if (t > best) best = t;
        t = __shfl_down_sync(0xffffffffu, best, 1, 8); if (t > best) best = t;
    }
    if (act && sub == 0) {
        int label = 256 - (int)(best & 0xFFull);   // argmax + 1, tie -> lowest class
        float tx = __ldg(pr + 0), ty = __ldg(pr + 1);
        float tw = __ldg(pr + 2), th = __ldg(pr + 3);
        float fs = __ldg(fsz + (size_t)n * 2);
        float4 an = *reinterpret_cast<const float4*>(ancs + (size_t)n * 4);
        float cx = 1.0f / (1.0f + expf(-tx)) / fs + an.x;
        float cy = 1.0f / (1.0f + expf(-ty)) / fs + an.y;
        float w  = expf(tw) * an.z;
        float hh = expf(th) * an.w;
        *reinterpret_cast<float4*>(outBoxes + (size_t)(b * KTOP + r) * 4) =
            make_float4(cx - 0.5f * w, cy - 0.5f * hh, cx + 0.5f * w, cy + 0.5f * hh);
        g_ls[b * KTOP + r] =
            make_float2((float)label, __uint_as_float((unsigned int)(my >> 32)));
    }
}

// ---------------------------------------------------------------------------
// k3: chip-wide suppression mask (grid (4,32) = 128 CTAs, 384 thr, ONE 64-IoU
// task per thread); then the last of each batch's 4 CTAs runs the greedy scan
// + final writes + scratch resets.
// ---------------------------------------------------------------------------
__global__ __launch_bounds__(384) void k3(float* __restrict__ outBoxes,
                                          float* __restrict__ outIds,
                                          float* __restrict__ outLabels,
                                          float* __restrict__ outScores) {
    const int q   = blockIdx.x;     // 0..3
    const int b   = blockIdx.y;
    const int tid = threadIdx.x;

    __shared__ float sl[KTOP], st[KTOP], sr[KTOP], sb[KTOP], sa[KTOP], ssc[KTOP];
    __shared__ int   slab[KTOP];

    // ---- stage boxes (offset coords) + scores/labels ----
    if (tid < KTOP) {
        float4 bx = *reinterpret_cast<const float4*>(outBoxes + (size_t)(b * KTOP + tid) * 4);
        float2 ls = g_ls[b * KTOP + tid];
        float off = 4.0f * ls.x;
        float l = bx.x + off, t0 = bx.y + off, r = bx.z + off, bt = bx.w + off;
        sl[tid] = l; st[tid] = t0; sr[tid] = r; sb[tid] = bt;
        sa[tid] = fmaxf(r - l, 0.0f) * fmaxf(bt - t0, 0.0f);
        ssc[tid]  = ls.y;
        slab[tid] = (int)ls.x;
    }
    __syncthreads();

    // ---- one (i, w) task per thread: 4 CTAs x 384 = 1536 >= 1500 ----
    {
        int task = q * 384 + tid;
        if (task < KTOP * 5) {
            int i = task % KTOP, w = task / KTOP;
            float li = sl[i], ti = st[i], ri = sr[i], bi = sb[i], ai = sa[i];
            unsigned long long bits = 0ull;
            int j0 = w * 64;
            int jend = min(j0 + 64, KTOP);
            for (int j = j0; j < jend; j++) {
                float ltx = fmaxf(li, sl[j]);
                float lty = fmaxf(ti, st[j]);
                float rbx = fminf(ri, sr[j]);
                float rby = fminf(bi, sb[j]);
                float iw = fmaxf(rbx - ltx, 0.0f);
                float ih = fmaxf(rby - lty, 0.0f);
                float inter = iw * ih;
                float iou = inter / (ai + sa[j] - inter + 1e-7f);
                if (iou > 0.3f) bits |= 1ull << (j - j0);
            }
            g_supp[(b * KTOP + i) * 5 + w] = bits;

            unsigned long long low = 0ull;     // suppressors with j < i
            int iw6 = i >> 6;
            if (w < iw6)       low = bits;
            else if (w == iw6) low = bits & ((1ull << (i & 63)) - 1ull);
            if (low) atomicOr(&g_anyLow[b * 5 + iw6], 1ull << (i & 63));
        }
    }

    // ---- last-block election (count to 4) ----
    __shared__ int isLast;
    __threadfence();
    __syncthreads();
    if (tid == 0) isLast = (atomicAdd(&g_done3[b], 1u) == 3);
    __syncthreads();
    if (!isLast) return;
    __threadfence();   // acquire: all batch-b supp/anyLow visible

    // ---- tail: stage supp, greedy scan, outputs, resets ----
    __shared__ unsigned long long ssup[KTOP * 5];   // 12 KB
    __shared__ unsigned long long keepw[5];
    for (int t = tid; t < KTOP * 5; t += 384)
        ssup[t] = g_supp[b * (KTOP * 5) + t];

    const int cc = min((int)g_cnt[b], KTOP);
    if (tid < KTOP && tid >= cc) {   // pathological pad (never with this data)
        *reinterpret_cast<float4*>(outBoxes + (size_t)(b * KTOP + tid) * 4) =
            make_float4(0.f, 0.f, 0.f, 0.f);
    }
    __syncthreads();

    if (tid == 0) {
        unsigned long long kw[5] = {0ull, 0ull, 0ull, 0ull, 0ull};
#pragma unroll
        for (int w = 0; w < 5; w++) {
            unsigned long long cur = 0ull;
            unsigned long long alw = g_anyLow[b * 5 + w];
            int lo = w * 64;
            int hi = min(cc, lo + 64);
            unsigned long long vmw = 0ull;
            if (hi > lo) {
                int nb = hi - lo;
                vmw = (nb >= 64) ? ~0ull : ((1ull << nb) - 1ull);
            }
            int jend = (w < 4) ? 64 : (KTOP - 256);
            for (int jj = 0; jj < jend; jj++) {
                unsigned long long bit = 1ull << jj;
                if (vmw & bit) {
                    if (!(alw & bit)) {
                        cur |= bit;        // no lower-ranked overlap at all
                    } else {
                        int i = w * 64 + jj;
                        unsigned long long s = (ssup[i * 5 + 0] & kw[0]) |
                                               (ssup[i * 5 + 1] & kw[1]) |
                                               (ssup[i * 5 + 2] & kw[2]) |
                                               (ssup[i * 5 + 3] & kw[3]) |
                                               (ssup[i * 5 + 4] & kw[4]) |
                                               (ssup[i * 5 + w] & cur);
                        if (s == 0ull) cur |= bit;
                    }
                }
            }
            kw[w] = cur;
        }
#pragma unroll
        for (int w = 0; w < 5; w++) keepw[w] = kw[w];
    }
    __syncthreads();

    if (tid < KTOP) {
        bool kp = (keepw[tid >> 6] >> (tid & 63)) & 1ull;
        outIds[b * KTOP + tid]    = (float)b;
        outScores[b * KTOP + tid] = kp ? ssc[tid] : 0.0f;
        outLabels[b * KTOP + tid] = kp ? (float)slab[tid] : 0.0f;
    }

    // restore zeros for next pass
    if (tid < 5)  g_anyLow[b * 5 + tid] = 0ull;
    if (tid == 0) g_done3[b] = 0u;
}

// ---------------------------------------------------------------------------
extern "C" void kernel_launch(void* const* d_in, const int* in_sizes, int n_in,
                              void* d_out, int out_size) {
    const float* p    = (const float*)d_in[0];
    const float* ancs = (const float*)d_in[1];
    const float* fsz  = (const float*)d_in[2];
    float* out = (float*)d_out;

    float* outIds    = out;
    float* outBoxes  = out + BATCH * KTOP;
    float* outLabels = out + BATCH * KTOP * 5;
    float* outScores = out + BATCH * KTOP * 6;

    dim3 grid1(NCTA1, BATCH);      // 12 x 32
    k1<<<grid1, 512>>>(p);
    dim3 grid2(CAP / 32, BATCH);   // 16 x 32
    k2<<<grid2, 256>>>(p, ancs, fsz, outBoxes);
    dim3 grid3(4, BATCH);          // 4 x 32
    k3<<<grid3, 384>>>(outBoxes, outIds, outLabels, outScores);
}